// round 1
// baseline (speedup 1.0000x reference)
#include <cuda_runtime.h>
#include <cstdint>

// Problem constants
#define NBATCH 8
#define CDIM   256
#define TDIM   16384
#define DCODES 512

// Tiling
#define BT 128          // t (queries) per block
#define BD 64           // codes per smem chunk
#define NTHREADS 256

// smem layout (floats)
#define XS_STRIDE 128                    // xs[c][t], 512B rows
#define RT_STRIDE 132                    // rowsT[c][t] padded (epilogue overlay of xs)
#define REGION_A_FLOATS (CDIM * RT_STRIDE)   // 33792 floats = 135168 B (>= xs size)
#define WS_STRIDE 68                     // ws[c][dl] padded, 272B rows (16B-aligned)
#define REGION_B_FLOATS (CDIM * WS_STRIDE)   // 17408 floats = 69632 B
#define SMEM_BYTES ((REGION_A_FLOATS + REGION_B_FLOATS) * 4)  // 204800 B

__device__ float g_hnorm[DCODES];

// ---------------------------------------------------------------------------
// Prologue: hnorm[d] = 0.5 * ||w_d||^2
// ---------------------------------------------------------------------------
__global__ void vq_hnorm_kernel(const float* __restrict__ dict) {
    int d = blockIdx.x * blockDim.x + threadIdx.x;
    if (d < DCODES) {
        const float4* row = reinterpret_cast<const float4*>(dict + (size_t)d * CDIM);
        float s = 0.f;
#pragma unroll
        for (int q = 0; q < CDIM / 4; q++) {
            float4 v = row[q];
            s += v.x * v.x + v.y * v.y + v.z * v.z + v.w * v.w;
        }
        g_hnorm[d] = 0.5f * s;
    }
}

// ---------------------------------------------------------------------------
// Packed f32x2 helpers (Blackwell dual-rate fp32)
// ---------------------------------------------------------------------------
__device__ __forceinline__ unsigned long long pack2(float x, float y) {
    unsigned long long r;
    asm("mov.b64 %0, {%1, %2};" : "=l"(r) : "f"(x), "f"(y));
    return r;
}
__device__ __forceinline__ void fma2(unsigned long long& d,
                                     unsigned long long a, unsigned long long b) {
    asm("fma.rn.f32x2 %0, %1, %2, %0;" : "+l"(d) : "l"(a), "l"(b));
}
__device__ __forceinline__ float2 unpack2(unsigned long long v) {
    float2 r;
    asm("mov.b64 {%0, %1}, %2;" : "=f"(r.x), "=f"(r.y) : "l"(v));
    return r;
}

// ---------------------------------------------------------------------------
// Main kernel: one block = 128 queries (one n, contiguous t) vs all 512 codes
// score_d = dot(x, w_d) - 0.5*||w_d||^2 ; argmax == reference argmin
// ---------------------------------------------------------------------------
__global__ __launch_bounds__(NTHREADS, 1)
void vq_main_kernel(const float* __restrict__ inputs,
                    const float* __restrict__ dict,
                    float* __restrict__ out) {
    extern __shared__ float smem[];
    float* xs = smem;                         // [CDIM][XS_STRIDE]
    float* ws = smem + REGION_A_FLOATS;       // [CDIM][WS_STRIDE]
    // reduction overlay (region B, after all compute chunks):
    float* s_red = ws;                        // [BT][16]
    int*   i_red = reinterpret_cast<int*>(ws + BT * 16);   // [BT][16]
    int*   fidx  = reinterpret_cast<int*>(ws + 2 * BT * 16); // [BT]

    const int tid = threadIdx.x;
    const int blk = blockIdx.x;
    const int tiles_per_n = TDIM / BT;        // 128
    const int n   = blk / tiles_per_n;
    const int tt0 = (blk % tiles_per_n) * BT;

    // ---- Stage x tile: xs[c][t] = inputs[n][c][tt0+t] (coalesced float4) ----
    {
        const float* xin = inputs + ((size_t)n * CDIM) * TDIM + tt0;
        int lane = tid & 31, wrow = tid >> 5;
#pragma unroll
        for (int j = 0; j < 32; j++) {
            int c = wrow + 8 * j;
            float4 v = *reinterpret_cast<const float4*>(xin + (size_t)c * TDIM + 4 * lane);
            *reinterpret_cast<float4*>(&xs[c * XS_STRIDE + 4 * lane]) = v;
        }
    }

    const int ti = tid & 15;   // t-group: owns t in {4ti..4ti+3} u {64+4ti..64+4ti+3}
    const int di = tid >> 4;   // d-group: owns d_local in {4di..4di+3} per chunk

    float best[8];
    int   bidx[8];
#pragma unroll
    for (int j = 0; j < 8; j++) { best[j] = -3.0e38f; bidx[j] = 0; }

    for (int d0 = 0; d0 < DCODES; d0 += BD) {
        __syncthreads();  // prior chunk compute done (and x staging done on iter 0)

        // Stage w chunk: ws[c][dl] = dict[d0+dl][c]  (coalesced LDG, 4-way STS)
#pragma unroll 8
        for (int j = 0; j < BD; j++) {
            float v = dict[(size_t)(d0 + j) * CDIM + tid];
            ws[tid * WS_STRIDE + j] = v;
        }
        __syncthreads();

        // ---- GEMM micro-tile: 8t x 4d per thread, f32x2 pairs over t ----
        unsigned long long acc[4][4];
#pragma unroll
        for (int p = 0; p < 4; p++)
#pragma unroll
            for (int k = 0; k < 4; k++) acc[p][k] = 0ull;

        const float* xrow0 = xs + ti * 4;
        const float* xrow1 = xs + 64 + ti * 4;
        const float* wrow  = ws + di * 4;

#pragma unroll 8
        for (int c = 0; c < CDIM; c++) {
            ulonglong2 xa = *reinterpret_cast<const ulonglong2*>(xrow0 + c * XS_STRIDE);
            ulonglong2 xb = *reinterpret_cast<const ulonglong2*>(xrow1 + c * XS_STRIDE);
            float4 wv = *reinterpret_cast<const float4*>(wrow + c * WS_STRIDE);
            unsigned long long w0 = pack2(wv.x, wv.x);
            unsigned long long w1 = pack2(wv.y, wv.y);
            unsigned long long w2 = pack2(wv.z, wv.z);
            unsigned long long w3 = pack2(wv.w, wv.w);
            fma2(acc[0][0], xa.x, w0); fma2(acc[0][1], xa.x, w1);
            fma2(acc[0][2], xa.x, w2); fma2(acc[0][3], xa.x, w3);
            fma2(acc[1][0], xa.y, w0); fma2(acc[1][1], xa.y, w1);
            fma2(acc[1][2], xa.y, w2); fma2(acc[1][3], xa.y, w3);
            fma2(acc[2][0], xb.x, w0); fma2(acc[2][1], xb.x, w1);
            fma2(acc[2][2], xb.x, w2); fma2(acc[2][3], xb.x, w3);
            fma2(acc[3][0], xb.y, w0); fma2(acc[3][1], xb.y, w1);
            fma2(acc[3][2], xb.y, w2); fma2(acc[3][3], xb.y, w3);
        }

        // ---- Finalize chunk: score = dot - hnorm, running argmax ----
#pragma unroll
        for (int k = 0; k < 4; k++) {
            int d = d0 + di * 4 + k;
            float hn = __ldg(&g_hnorm[d]);
#pragma unroll
            for (int p = 0; p < 4; p++) {
                float2 s = unpack2(acc[p][k]);
                float v0 = s.x - hn;
                float v1 = s.y - hn;
                int j0 = 2 * p, j1 = 2 * p + 1;
                if (v0 > best[j0]) { best[j0] = v0; bidx[j0] = d; }
                if (v1 > best[j1]) { best[j1] = v1; bidx[j1] = d; }
            }
        }
    }

    __syncthreads();  // all compute reads of ws done before overlay

    // ---- Cross-thread (over di) argmax reduction per t ----
#pragma unroll
    for (int j = 0; j < 8; j++) {
        int t = (j < 4) ? (ti * 4 + j) : (64 + ti * 4 + (j - 4));
        s_red[t * 16 + di] = best[j];
        i_red[t * 16 + di] = bidx[j];
    }
    __syncthreads();

    const size_t E = (size_t)NBATCH * CDIM * TDIM;
    if (tid < BT) {
        float bs = -3.0e38f; int bi = 0x7fffffff;
        for (int q = 0; q < 16; q++) {
            float s = s_red[tid * 16 + q];
            int  ix = i_red[tid * 16 + q];
            if (s > bs || (s == bs && ix < bi)) { bs = s; bi = ix; }
        }
        fidx[tid] = bi;
        // idxs output (as float, exact for idx < 512)
        out[2 * E + (size_t)n * TDIM + tt0 + tid] = (float)bi;
    }
    __syncthreads();

    // ---- Stage selected dict rows transposed: rowsT[c][t] (overlay region A) ----
    {
        float* rowsT = smem;
        int lane = tid & 31, w = tid >> 5;
        for (int t = w; t < BT; t += 8) {
            const float* drow = dict + (size_t)fidx[t] * CDIM;
#pragma unroll
            for (int q = 0; q < CDIM; q += 32) {
                float v = drow[q + lane];          // coalesced LDG (dict hot in L2)
                rowsT[(q + lane) * RT_STRIDE + t] = v;  // 4-way STS, small volume
            }
        }
    }
    __syncthreads();

    // ---- Write embedded + passthrough, float4-coalesced over t ----
    {
        const float* rowsT = smem;
        float* out_e = out;
        float* out_p = out + E;
        int g = tid & 31, cw = tid >> 5;
#pragma unroll
        for (int j = 0; j < 32; j++) {
            int c = cw + 8 * j;
            float4 v = *reinterpret_cast<const float4*>(&rowsT[c * RT_STRIDE + 4 * g]);
            size_t o = ((size_t)n * CDIM + c) * TDIM + tt0 + 4 * g;
            *reinterpret_cast<float4*>(out_e + o) = v;
            *reinterpret_cast<float4*>(out_p + o) = v;
        }
    }
}

// ---------------------------------------------------------------------------
extern "C" void kernel_launch(void* const* d_in, const int* in_sizes, int n_in,
                              void* d_out, int out_size) {
    const float* inputs = (const float*)d_in[0];
    const float* dict   = (const float*)d_in[1];
    float* out = (float*)d_out;

    cudaFuncSetAttribute(vq_main_kernel,
                         cudaFuncAttributeMaxDynamicSharedMemorySize, SMEM_BYTES);

    vq_hnorm_kernel<<<4, 128>>>(dict);
    vq_main_kernel<<<(NBATCH * TDIM) / BT, NTHREADS, SMEM_BYTES>>>(inputs, dict, out);
}